// round 3
// baseline (speedup 1.0000x reference)
#include <cuda_runtime.h>
#include <cuda_bf16.h>

typedef unsigned long long ull;

#define H 256
#define S 200
#define BSZ 1024
#define BT 8
#define NITEMS 50000
#define KC 50            // k-pair slabs of W1/W2 cached in smem (of 128)

// ---------------- device globals (scratch; no allocs allowed) ----------------
__device__ ull   g_WhhP[128 * 768];          // packed (k,k+1) pairs, kp-major
__device__ ull   g_W1P[128 * 256];
__device__ ull   g_W2P[128 * 256];
__device__ float g_Etab[(size_t)NITEMS * 768];  // item_emb @ W_ih^T + b_ih
__device__ float g_hfin[BSZ * H];

// ---------------- f32x2 helpers ----------------
__device__ __forceinline__ void ffma2(ull& d, ull a, ull b) {
    asm("fma.rn.f32x2 %0, %1, %2, %3;" : "=l"(d) : "l"(a), "l"(b), "l"(d));
}
__device__ __forceinline__ ull pack2(float lo, float hi) {
    ull r; asm("mov.b64 %0, {%1, %2};" : "=l"(r) : "f"(lo), "f"(hi)); return r;
}
__device__ __forceinline__ void unpack2(ull v, float& lo, float& hi) {
    asm("mov.b64 {%0, %1}, %2;" : "=f"(lo), "=f"(hi) : "l"(v));
}
__device__ __forceinline__ float hsum2(ull v) {
    float lo, hi; unpack2(v, lo, hi); return lo + hi;
}
__device__ __forceinline__ float sigm(float v) { return 1.0f / (1.0f + __expf(-v)); }
__device__ __forceinline__ float ftanh(float v) {
    float e = __expf(2.0f * v);
    return 1.0f - 2.0f / (e + 1.0f);
}

// ---------------- weight packing ----------------
__global__ void prep_pack(const float* __restrict__ W_hh,
                          const float* __restrict__ W1,
                          const float* __restrict__ W2)
{
    int i = blockIdx.x * blockDim.x + threadIdx.x;
    if (i < 128 * 768) {
        int kp = i / 768, m = i % 768;
        g_WhhP[i] = pack2(W_hh[m * H + 2 * kp], W_hh[m * H + 2 * kp + 1]);
    }
    if (i < 128 * 256) {
        int kp = i / 256, jo = i % 256;
        g_W1P[i] = pack2(W1[jo * H + 2 * kp], W1[jo * H + 2 * kp + 1]);
        g_W2P[i] = pack2(W2[jo * H + 2 * kp], W2[jo * H + 2 * kp + 1]);
    }
}

// ---------------- generic C[M,N] = A[M,256] @ B[N,256]^T + bias ----------------
#define GM 32
#define GN 128

__global__ void __launch_bounds__(256) gemm_nt(
    const float* __restrict__ A, const float* __restrict__ B,
    const float* __restrict__ bias, float* __restrict__ C,
    int M, int N)
{
    __shared__ float shA[GM][H];     // 32 KB
    __shared__ float shW[8][136];    // padded, 16B-aligned rows

    const int n0 = blockIdx.x * GN;
    const int m0 = blockIdx.y * GM;
    const int tid = threadIdx.x;

#pragma unroll
    for (int it = 0; it < GM; it++) {
        int idx = tid + it * 256;
        int r = idx >> 8, c = idx & 255;
        int m = m0 + r;
        shA[r][c] = (m < M) ? A[(size_t)m * H + c] : 0.f;
    }

    const int tn = tid & 31;
    const int tb = tid >> 5;
    const int nl0 = tn * 4;

    ull accP[4][2];
#pragma unroll
    for (int bb = 0; bb < 4; bb++) { accP[bb][0] = 0ull; accP[bb][1] = 0ull; }

    __syncthreads();

    for (int k0 = 0; k0 < H; k0 += 8) {
#pragma unroll
        for (int i = 0; i < 4; i++) {
            int idx = tid + i * 256;         // 0..1023 -> 128 n x 8 k
            int nl = idx >> 3, kc = idx & 7;
            int n = n0 + nl;
            shW[kc][nl] = (n < N) ? B[(size_t)n * H + k0 + kc] : 0.f;
        }
        __syncthreads();
#pragma unroll
        for (int kc = 0; kc < 8; kc++) {
            ulonglong2 wv = *(const ulonglong2*)&shW[kc][nl0];
#pragma unroll
            for (int bb = 0; bb < 4; bb++) {
                float hb = shA[tb * 4 + bb][k0 + kc];
                ull hp = pack2(hb, hb);
                ffma2(accP[bb][0], hp, wv.x);
                ffma2(accP[bb][1], hp, wv.y);
            }
        }
        __syncthreads();
    }

    const int nbase = n0 + nl0;
#pragma unroll
    for (int bb = 0; bb < 4; bb++) {
        int m = m0 + tb * 4 + bb;
        if (m >= M) continue;
        float o0, o1, o2, o3;
        unpack2(accP[bb][0], o0, o1);
        unpack2(accP[bb][1], o2, o3);
        if (nbase + 3 < N) {
            float4 o;
            o.x = o0 + bias[nbase + 0];
            o.y = o1 + bias[nbase + 1];
            o.z = o2 + bias[nbase + 2];
            o.w = o3 + bias[nbase + 3];
            *(float4*)&C[(size_t)m * N + nbase] = o;
        } else {
            float ov[4] = {o0, o1, o2, o3};
#pragma unroll
            for (int nn = 0; nn < 4; nn++) {
                int n = nbase + nn;
                if (n < N) C[(size_t)m * N + n] = ov[nn] + bias[n];
            }
        }
    }
}

// ---------------- ODE matmul layer: out[r] = sum_k src[r][k] * W[j][k] ----------------
__device__ __forceinline__ void mm_ode(const float (*__restrict__ src)[H],
                                       const ull* __restrict__ ws,   // smem, kp < KC
                                       const ull* __restrict__ wg,   // global, full
                                       int j, float* out)
{
    ull acc[BT];
#pragma unroll
    for (int r = 0; r < BT; r++) acc[r] = 0ull;

#pragma unroll 2
    for (int kp = 0; kp < KC; kp += 2) {
        ulonglong2 sv[BT];
#pragma unroll
        for (int r = 0; r < BT; r++) sv[r] = *(const ulonglong2*)&src[r][2 * kp];
        ull w0 = ws[kp * H + j];
        ull w1 = ws[(kp + 1) * H + j];
#pragma unroll
        for (int r = 0; r < BT; r++) { ffma2(acc[r], sv[r].x, w0); ffma2(acc[r], sv[r].y, w1); }
    }
#pragma unroll 2
    for (int kp = KC; kp < 128; kp += 2) {
        ulonglong2 sv[BT];
#pragma unroll
        for (int r = 0; r < BT; r++) sv[r] = *(const ulonglong2*)&src[r][2 * kp];
        ull w0 = wg[kp * H + j];
        ull w1 = wg[(kp + 1) * H + j];
#pragma unroll
        for (int r = 0; r < BT; r++) { ffma2(acc[r], sv[r].x, w0); ffma2(acc[r], sv[r].y, w1); }
    }
#pragma unroll
    for (int r = 0; r < BT; r++) out[r] = hsum2(acc[r]);
}

__device__ __forceinline__ void ode_f(const float (*__restrict__ src)[H],
                                      float (*__restrict__ sh_a)[H],
                                      const ull* __restrict__ sW1,
                                      const ull* __restrict__ sW2,
                                      float* kv, int j, float b1j, float b2j)
{
    float t1[BT];
    mm_ode(src, sW1, g_W1P, j, t1);
#pragma unroll
    for (int r = 0; r < BT; r++) sh_a[r][j] = ftanh(t1[r] + b1j);
    __syncthreads();
    mm_ode(sh_a, sW2, g_W2P, j, kv);
#pragma unroll
    for (int r = 0; r < BT; r++) kv[r] += b2j;
}

// ---------------- recurrent kernel ----------------
__global__ void __launch_bounds__(256) rec_kernel(
    const int* __restrict__ x, const float* __restrict__ tt,
    const float* __restrict__ b_hh,
    const float* __restrict__ b1, const float* __restrict__ b2)
{
    extern __shared__ ull dynsmem[];
    ull* sW1 = dynsmem;                          // KC*256 ull
    ull* sW2 = dynsmem + KC * H;                 // KC*256 ull
    float* fbase = (float*)(dynsmem + 2 * KC * H);
    float (*sh_h)[H] = (float (*)[H])fbase;
    float (*sh_a)[H] = (float (*)[H])(fbase + BT * H);
    float (*sh_t)[H] = (float (*)[H])(fbase + 2 * BT * H);
    int*   sh_it = (int*)(fbase + 3 * BT * H);
    float* sh_dt = (float*)(sh_it + BT);

    const int j = threadIdx.x;
    const int b0 = blockIdx.x * BT;

    // cache first KC k-pair slabs of W1/W2 in smem (reused 200 steps x 4 evals)
    for (int i = j; i < KC * H; i += H) { sW1[i] = g_W1P[i]; sW2[i] = g_W2P[i]; }

    const float bhhr = b_hh[j], bhhz = b_hh[H + j], bhhn = b_hh[2 * H + j];
    const float b1j = b1[j], b2j = b2[j];

#pragma unroll
    for (int r = 0; r < BT; r++) sh_h[r][j] = 0.f;
    float hnew[BT];
#pragma unroll
    for (int r = 0; r < BT; r++) hnew[r] = 0.f;
    __syncthreads();

    const ull* __restrict__ whh = g_WhhP;

    for (int s = 0; s < S; s++) {
        if (j < BT) {
            sh_it[j] = x[(b0 + j) * S + s];
            float tc = tt[(b0 + j) * S + s];
            float d = 0.f;
            if (s < S - 1) {
                float tn = tt[(b0 + j) * S + s + 1];
                d = fmaxf(tn, tc + 1e-5f) - tc;
            }
            sh_dt[j] = d;
        }
        __syncthreads();   // (A)

        // issue input-gate gathers early (long-latency global loads)
        float giR[BT], giZ[BT], giN[BT];
#pragma unroll
        for (int r = 0; r < BT; r++) {
            const float* e = g_Etab + (size_t)sh_it[r] * 768;
            giR[r] = e[j];
            giZ[r] = e[H + j];
            giN[r] = e[2 * H + j];
        }

        // ---- hidden-state gate matmul: h @ W_hh^T (packed pairs over k) ----
        ull aR[BT], aZ[BT], aN[BT];
#pragma unroll
        for (int r = 0; r < BT; r++) { aR[r] = 0ull; aZ[r] = 0ull; aN[r] = 0ull; }

#pragma unroll 2
        for (int kp = 0; kp < 128; kp += 2) {
            ulonglong2 hv[BT];
#pragma unroll
            for (int r = 0; r < BT; r++) hv[r] = *(const ulonglong2*)&sh_h[r][2 * kp];
            ull w0R = whh[kp * 768 + j];
            ull w0Z = whh[kp * 768 + H + j];
            ull w0N = whh[kp * 768 + 2 * H + j];
            ull w1R = whh[(kp + 1) * 768 + j];
            ull w1Z = whh[(kp + 1) * 768 + H + j];
            ull w1N = whh[(kp + 1) * 768 + 2 * H + j];
#pragma unroll
            for (int r = 0; r < BT; r++) {
                ffma2(aR[r], hv[r].x, w0R);
                ffma2(aZ[r], hv[r].x, w0Z);
                ffma2(aN[r], hv[r].x, w0N);
                ffma2(aR[r], hv[r].y, w1R);
                ffma2(aZ[r], hv[r].y, w1Z);
                ffma2(aN[r], hv[r].y, w1N);
            }
        }

        // ---- GRU elementwise (gate order r,z,n) ----
#pragma unroll
        for (int r = 0; r < BT; r++) {
            float rg = sigm(giR[r] + hsum2(aR[r]) + bhhr);
            float zg = sigm(giZ[r] + hsum2(aZ[r]) + bhhz);
            float ng = ftanh(giN[r] + rg * (hsum2(aN[r]) + bhhn));
            hnew[r] = (1.f - zg) * ng + zg * sh_h[r][j];
        }
        __syncthreads();   // (B) everyone done reading sh_h
#pragma unroll
        for (int r = 0; r < BT; r++) sh_h[r][j] = hnew[r];
        __syncthreads();   // (C)

        // ---- RK4 ----
        float dtl[BT];
#pragma unroll
        for (int r = 0; r < BT; r++) dtl[r] = sh_dt[r];

        float kv[BT], ksum[BT];

        ode_f(sh_h, sh_a, sW1, sW2, kv, j, b1j, b2j);          // k1
#pragma unroll
        for (int r = 0; r < BT; r++) {
            ksum[r] = kv[r];
            sh_t[r][j] = hnew[r] + 0.5f * dtl[r] * kv[r];
        }
        __syncthreads();

        ode_f(sh_t, sh_a, sW1, sW2, kv, j, b1j, b2j);          // k2
#pragma unroll
        for (int r = 0; r < BT; r++) {
            ksum[r] += 2.f * kv[r];
            sh_t[r][j] = hnew[r] + 0.5f * dtl[r] * kv[r];
        }
        __syncthreads();

        ode_f(sh_t, sh_a, sW1, sW2, kv, j, b1j, b2j);          // k3
#pragma unroll
        for (int r = 0; r < BT; r++) {
            ksum[r] += 2.f * kv[r];
            sh_t[r][j] = hnew[r] + dtl[r] * kv[r];
        }
        __syncthreads();

        ode_f(sh_t, sh_a, sW1, sW2, kv, j, b1j, b2j);          // k4
#pragma unroll
        for (int r = 0; r < BT; r++) {
            ksum[r] += kv[r];
            hnew[r] = hnew[r] + (dtl[r] * (1.f / 6.f)) * ksum[r];
            sh_h[r][j] = hnew[r];
        }
        // next-iteration sync (A) fences sh_h / sh_it reuse
    }

#pragma unroll
    for (int r = 0; r < BT; r++) g_hfin[(b0 + r) * H + j] = hnew[r];
}

// ---------------- launch ----------------
extern "C" void kernel_launch(void* const* d_in, const int* in_sizes, int n_in,
                              void* d_out, int out_size)
{
    const int*   x      = (const int*)d_in[0];
    const float* t      = (const float*)d_in[1];
    const float* emb    = (const float*)d_in[2];
    const float* W_ih   = (const float*)d_in[3];
    const float* W_hh   = (const float*)d_in[4];
    const float* b_ih   = (const float*)d_in[5];
    const float* b_hh   = (const float*)d_in[6];
    const float* W1     = (const float*)d_in[7];
    const float* b1     = (const float*)d_in[8];
    const float* W2     = (const float*)d_in[9];
    const float* b2     = (const float*)d_in[10];
    const float* W_head = (const float*)d_in[11];
    const float* b_head = (const float*)d_in[12];
    float* out = (float*)d_out;

    float* etab_ptr = nullptr;
    float* hfin_ptr = nullptr;
    cudaGetSymbolAddress((void**)&etab_ptr, g_Etab);
    cudaGetSymbolAddress((void**)&hfin_ptr, g_hfin);

    const int smem_bytes = 2 * KC * H * (int)sizeof(ull) + 3 * BT * H * (int)sizeof(float)
                         + BT * (int)(sizeof(int) + sizeof(float));
    cudaFuncSetAttribute(rec_kernel, cudaFuncAttributeMaxDynamicSharedMemorySize, smem_bytes);

    prep_pack<<<(128 * 768 + 255) / 256, 256>>>(W_hh, W1, W2);

    // Etab = item_emb @ W_ih^T + b_ih   [50000, 768]
    dim3 ge(768 / GN, (NITEMS + GM - 1) / GM);
    gemm_nt<<<ge, 256>>>(emb, W_ih, b_ih, etab_ptr, NITEMS, 768);

    rec_kernel<<<BSZ / BT, H, smem_bytes>>>(x, t, b_hh, b1, b2);

    // out = h_fin @ W_head^T + b_head   [1024, 50000]
    dim3 gh((NITEMS + GN - 1) / GN, BSZ / GM);
    gemm_nt<<<gh, 256>>>(hfin_ptr, W_head, b_head, out, BSZ, NITEMS);
}

// round 4
// speedup vs baseline: 1.5358x; 1.5358x over previous
#include <cuda_runtime.h>
#include <cuda_bf16.h>

typedef unsigned long long ull;

#define H 256
#define S 200
#define BSZ 1024
#define BT 8
#define NITEMS 50000
#define KC 50            // k-pair slabs of W1/W2 cached in smem (of 128)

// ---------------- device globals (scratch; no allocs allowed) ----------------
__device__ ull   g_WhhP[128 * 768];          // packed (k,k+1) pairs, kp-major
__device__ ull   g_W1P[128 * 256];
__device__ ull   g_W2P[128 * 256];
__device__ float g_Etab[(size_t)NITEMS * 768];  // item_emb @ W_ih^T + b_ih
__device__ float g_hfin[BSZ * H];

// ---------------- f32x2 helpers ----------------
__device__ __forceinline__ void ffma2(ull& d, ull a, ull b) {
    asm("fma.rn.f32x2 %0, %1, %2, %3;" : "=l"(d) : "l"(a), "l"(b), "l"(d));
}
__device__ __forceinline__ ull pack2(float lo, float hi) {
    ull r; asm("mov.b64 %0, {%1, %2};" : "=l"(r) : "f"(lo), "f"(hi)); return r;
}
__device__ __forceinline__ void unpack2(ull v, float& lo, float& hi) {
    asm("mov.b64 {%0, %1}, %2;" : "=f"(lo), "=f"(hi) : "l"(v));
}
__device__ __forceinline__ float hsum2(ull v) {
    float lo, hi; unpack2(v, lo, hi); return lo + hi;
}
__device__ __forceinline__ float sigm(float v) { return 1.0f / (1.0f + __expf(-v)); }
__device__ __forceinline__ float ftanh(float v) {
    float e = __expf(2.0f * v);
    return 1.0f - 2.0f / (e + 1.0f);
}

// ---------------- weight packing ----------------
__global__ void prep_pack(const float* __restrict__ W_hh,
                          const float* __restrict__ W1,
                          const float* __restrict__ W2)
{
    int i = blockIdx.x * blockDim.x + threadIdx.x;
    if (i < 128 * 768) {
        int kp = i / 768, m = i % 768;
        g_WhhP[i] = pack2(W_hh[m * H + 2 * kp], W_hh[m * H + 2 * kp + 1]);
    }
    if (i < 128 * 256) {
        int kp = i / 256, jo = i % 256;
        g_W1P[i] = pack2(W1[jo * H + 2 * kp], W1[jo * H + 2 * kp + 1]);
        g_W2P[i] = pack2(W2[jo * H + 2 * kp], W2[jo * H + 2 * kp + 1]);
    }
}

// ---------------- generic C[M,N] = A[M,256] @ B[N,256]^T + bias ----------------
#define GM 32
#define GN 128

__global__ void __launch_bounds__(256) gemm_nt(
    const float* __restrict__ A, const float* __restrict__ B,
    const float* __restrict__ bias, float* __restrict__ C,
    int M, int N)
{
    __shared__ float shA[GM][H];     // 32 KB
    __shared__ float shW[8][136];    // padded, 16B-aligned rows

    const int n0 = blockIdx.x * GN;
    const int m0 = blockIdx.y * GM;
    const int tid = threadIdx.x;

#pragma unroll
    for (int it = 0; it < GM; it++) {
        int idx = tid + it * 256;
        int r = idx >> 8, c = idx & 255;
        int m = m0 + r;
        shA[r][c] = (m < M) ? A[(size_t)m * H + c] : 0.f;
    }

    const int tn = tid & 31;
    const int tb = tid >> 5;
    const int nl0 = tn * 4;

    ull accP[4][2];
#pragma unroll
    for (int bb = 0; bb < 4; bb++) { accP[bb][0] = 0ull; accP[bb][1] = 0ull; }

    __syncthreads();

    for (int k0 = 0; k0 < H; k0 += 8) {
#pragma unroll
        for (int i = 0; i < 4; i++) {
            int idx = tid + i * 256;         // 0..1023 -> 128 n x 8 k
            int nl = idx >> 3, kc = idx & 7;
            int n = n0 + nl;
            shW[kc][nl] = (n < N) ? B[(size_t)n * H + k0 + kc] : 0.f;
        }
        __syncthreads();
#pragma unroll
        for (int kc = 0; kc < 8; kc++) {
            ulonglong2 wv = *(const ulonglong2*)&shW[kc][nl0];
#pragma unroll
            for (int bb = 0; bb < 4; bb++) {
                float hb = shA[tb * 4 + bb][k0 + kc];
                ull hp = pack2(hb, hb);
                ffma2(accP[bb][0], hp, wv.x);
                ffma2(accP[bb][1], hp, wv.y);
            }
        }
        __syncthreads();
    }

    const int nbase = n0 + nl0;
#pragma unroll
    for (int bb = 0; bb < 4; bb++) {
        int m = m0 + tb * 4 + bb;
        if (m >= M) continue;
        float o0, o1, o2, o3;
        unpack2(accP[bb][0], o0, o1);
        unpack2(accP[bb][1], o2, o3);
        if (nbase + 3 < N) {
            float4 o;
            o.x = o0 + bias[nbase + 0];
            o.y = o1 + bias[nbase + 1];
            o.z = o2 + bias[nbase + 2];
            o.w = o3 + bias[nbase + 3];
            *(float4*)&C[(size_t)m * N + nbase] = o;
        } else {
            float ov[4] = {o0, o1, o2, o3};
#pragma unroll
            for (int nn = 0; nn < 4; nn++) {
                int n = nbase + nn;
                if (n < N) C[(size_t)m * N + n] = ov[nn] + bias[n];
            }
        }
    }
}

// ---------------- ODE matmul layer: out[r] = sum_k src[r][k] * W[j][k] ----------------
__device__ __forceinline__ void mm_ode(const float (*__restrict__ src)[H],
                                       const ull* __restrict__ ws,   // smem, kp < KC
                                       const ull* __restrict__ wg,   // global, full
                                       int j, float* out)
{
    ull acc[BT];
#pragma unroll
    for (int r = 0; r < BT; r++) acc[r] = 0ull;

#pragma unroll 2
    for (int kp = 0; kp < KC; kp += 2) {
        ulonglong2 sv[BT];
#pragma unroll
        for (int r = 0; r < BT; r++) sv[r] = *(const ulonglong2*)&src[r][2 * kp];
        ull w0 = ws[kp * H + j];
        ull w1 = ws[(kp + 1) * H + j];
#pragma unroll
        for (int r = 0; r < BT; r++) { ffma2(acc[r], sv[r].x, w0); ffma2(acc[r], sv[r].y, w1); }
    }
#pragma unroll 2
    for (int kp = KC; kp < 128; kp += 2) {
        ulonglong2 sv[BT];
#pragma unroll
        for (int r = 0; r < BT; r++) sv[r] = *(const ulonglong2*)&src[r][2 * kp];
        ull w0 = wg[kp * H + j];
        ull w1 = wg[(kp + 1) * H + j];
#pragma unroll
        for (int r = 0; r < BT; r++) { ffma2(acc[r], sv[r].x, w0); ffma2(acc[r], sv[r].y, w1); }
    }
#pragma unroll
    for (int r = 0; r < BT; r++) out[r] = hsum2(acc[r]);
}

__device__ __forceinline__ void ode_f(const float (*__restrict__ src)[H],
                                      float (*__restrict__ sh_a)[H],
                                      const ull* __restrict__ sW1,
                                      const ull* __restrict__ sW2,
                                      float* kv, int j, float b1j, float b2j)
{
    float t1[BT];
    mm_ode(src, sW1, g_W1P, j, t1);
#pragma unroll
    for (int r = 0; r < BT; r++) sh_a[r][j] = ftanh(t1[r] + b1j);
    __syncthreads();
    mm_ode(sh_a, sW2, g_W2P, j, kv);
#pragma unroll
    for (int r = 0; r < BT; r++) kv[r] += b2j;
}

// ---------------- recurrent kernel ----------------
__global__ void __launch_bounds__(256) rec_kernel(
    const int* __restrict__ x, const float* __restrict__ tt,
    const float* __restrict__ b_hh,
    const float* __restrict__ b1, const float* __restrict__ b2)
{
    extern __shared__ ull dynsmem[];
    ull* sW1 = dynsmem;                          // KC*256 ull
    ull* sW2 = dynsmem + KC * H;                 // KC*256 ull
    float* fbase = (float*)(dynsmem + 2 * KC * H);
    float (*sh_h)[H] = (float (*)[H])fbase;
    float (*sh_a)[H] = (float (*)[H])(fbase + BT * H);
    float (*sh_t)[H] = (float (*)[H])(fbase + 2 * BT * H);
    int*   sh_it = (int*)(fbase + 3 * BT * H);
    float* sh_dt = (float*)(sh_it + BT);

    const int j = threadIdx.x;
    const int b0 = blockIdx.x * BT;

    // cache first KC k-pair slabs of W1/W2 in smem (reused 200 steps x 4 evals)
    for (int i = j; i < KC * H; i += H) { sW1[i] = g_W1P[i]; sW2[i] = g_W2P[i]; }

    const float bhhr = b_hh[j], bhhz = b_hh[H + j], bhhn = b_hh[2 * H + j];
    const float b1j = b1[j], b2j = b2[j];

#pragma unroll
    for (int r = 0; r < BT; r++) sh_h[r][j] = 0.f;
    float hnew[BT];
#pragma unroll
    for (int r = 0; r < BT; r++) hnew[r] = 0.f;
    __syncthreads();

    const ull* __restrict__ whh = g_WhhP;

    for (int s = 0; s < S; s++) {
        if (j < BT) {
            sh_it[j] = x[(b0 + j) * S + s];
            float tc = tt[(b0 + j) * S + s];
            float d = 0.f;
            if (s < S - 1) {
                float tn = tt[(b0 + j) * S + s + 1];
                d = fmaxf(tn, tc + 1e-5f) - tc;
            }
            sh_dt[j] = d;
        }
        __syncthreads();   // (A)

        // issue input-gate gathers early (long-latency global loads)
        float giR[BT], giZ[BT], giN[BT];
#pragma unroll
        for (int r = 0; r < BT; r++) {
            const float* e = g_Etab + (size_t)sh_it[r] * 768;
            giR[r] = e[j];
            giZ[r] = e[H + j];
            giN[r] = e[2 * H + j];
        }

        // ---- hidden-state gate matmul: h @ W_hh^T (packed pairs over k) ----
        ull aR[BT], aZ[BT], aN[BT];
#pragma unroll
        for (int r = 0; r < BT; r++) { aR[r] = 0ull; aZ[r] = 0ull; aN[r] = 0ull; }

#pragma unroll 2
        for (int kp = 0; kp < 128; kp += 2) {
            ulonglong2 hv[BT];
#pragma unroll
            for (int r = 0; r < BT; r++) hv[r] = *(const ulonglong2*)&sh_h[r][2 * kp];
            ull w0R = whh[kp * 768 + j];
            ull w0Z = whh[kp * 768 + H + j];
            ull w0N = whh[kp * 768 + 2 * H + j];
            ull w1R = whh[(kp + 1) * 768 + j];
            ull w1Z = whh[(kp + 1) * 768 + H + j];
            ull w1N = whh[(kp + 1) * 768 + 2 * H + j];
#pragma unroll
            for (int r = 0; r < BT; r++) {
                ffma2(aR[r], hv[r].x, w0R);
                ffma2(aZ[r], hv[r].x, w0Z);
                ffma2(aN[r], hv[r].x, w0N);
                ffma2(aR[r], hv[r].y, w1R);
                ffma2(aZ[r], hv[r].y, w1Z);
                ffma2(aN[r], hv[r].y, w1N);
            }
        }

        // ---- GRU elementwise (gate order r,z,n) ----
#pragma unroll
        for (int r = 0; r < BT; r++) {
            float rg = sigm(giR[r] + hsum2(aR[r]) + bhhr);
            float zg = sigm(giZ[r] + hsum2(aZ[r]) + bhhz);
            float ng = ftanh(giN[r] + rg * (hsum2(aN[r]) + bhhn));
            hnew[r] = (1.f - zg) * ng + zg * sh_h[r][j];
        }
        __syncthreads();   // (B) everyone done reading sh_h
#pragma unroll
        for (int r = 0; r < BT; r++) sh_h[r][j] = hnew[r];
        __syncthreads();   // (C)

        // ---- RK4 ----
        float dtl[BT];
#pragma unroll
        for (int r = 0; r < BT; r++) dtl[r] = sh_dt[r];

        float kv[BT], ksum[BT];

        ode_f(sh_h, sh_a, sW1, sW2, kv, j, b1j, b2j);          // k1
#pragma unroll
        for (int r = 0; r < BT; r++) {
            ksum[r] = kv[r];
            sh_t[r][j] = hnew[r] + 0.5f * dtl[r] * kv[r];
        }
        __syncthreads();

        ode_f(sh_t, sh_a, sW1, sW2, kv, j, b1j, b2j);          // k2
#pragma unroll
        for (int r = 0; r < BT; r++) {
            ksum[r] += 2.f * kv[r];
            sh_t[r][j] = hnew[r] + 0.5f * dtl[r] * kv[r];
        }
        __syncthreads();

        ode_f(sh_t, sh_a, sW1, sW2, kv, j, b1j, b2j);          // k3
#pragma unroll
        for (int r = 0; r < BT; r++) {
            ksum[r] += 2.f * kv[r];
            sh_t[r][j] = hnew[r] + dtl[r] * kv[r];
        }
        __syncthreads();

        ode_f(sh_t, sh_a, sW1, sW2, kv, j, b1j, b2j);          // k4
#pragma unroll
        for (int r = 0; r < BT; r++) {
            ksum[r] += kv[r];
            hnew[r] = hnew[r] + (dtl[r] * (1.f / 6.f)) * ksum[r];
            sh_h[r][j] = hnew[r];
        }
        // next-iteration sync (A) fences sh_h / sh_it reuse
    }

#pragma unroll
    for (int r = 0; r < BT; r++) g_hfin[(b0 + r) * H + j] = hnew[r];
}

// ---------------- launch ----------------
extern "C" void kernel_launch(void* const* d_in, const int* in_sizes, int n_in,
                              void* d_out, int out_size)
{
    const int*   x      = (const int*)d_in[0];
    const float* t      = (const float*)d_in[1];
    const float* emb    = (const float*)d_in[2];
    const float* W_ih   = (const float*)d_in[3];
    const float* W_hh   = (const float*)d_in[4];
    const float* b_ih   = (const float*)d_in[5];
    const float* b_hh   = (const float*)d_in[6];
    const float* W1     = (const float*)d_in[7];
    const float* b1     = (const float*)d_in[8];
    const float* W2     = (const float*)d_in[9];
    const float* b2     = (const float*)d_in[10];
    const float* W_head = (const float*)d_in[11];
    const float* b_head = (const float*)d_in[12];
    float* out = (float*)d_out;

    float* etab_ptr = nullptr;
    float* hfin_ptr = nullptr;
    cudaGetSymbolAddress((void**)&etab_ptr, g_Etab);
    cudaGetSymbolAddress((void**)&hfin_ptr, g_hfin);

    const int smem_bytes = 2 * KC * H * (int)sizeof(ull) + 3 * BT * H * (int)sizeof(float)
                         + BT * (int)(sizeof(int) + sizeof(float));
    cudaFuncSetAttribute(rec_kernel, cudaFuncAttributeMaxDynamicSharedMemorySize, smem_bytes);

    prep_pack<<<(128 * 768 + 255) / 256, 256>>>(W_hh, W1, W2);

    // Etab = item_emb @ W_ih^T + b_ih   [50000, 768]
    dim3 ge(768 / GN, (NITEMS + GM - 1) / GM);
    gemm_nt<<<ge, 256>>>(emb, W_ih, b_ih, etab_ptr, NITEMS, 768);

    rec_kernel<<<BSZ / BT, H, smem_bytes>>>(x, t, b_hh, b1, b2);

    // out = h_fin @ W_head^T + b_head   [1024, 50000]
    dim3 gh((NITEMS + GN - 1) / GN, BSZ / GM);
    gemm_nt<<<gh, 256>>>(hfin_ptr, W_head, b_head, out, BSZ, NITEMS);
}